// round 13
// baseline (speedup 1.0000x reference)
#include <cuda_runtime.h>
#include <cuda_fp16.h>
#include <cstdint>

#define HQ   16
#define HKV  8
#define SEQ  2048
#define DIM  128

// ---------------- device scratch ----------------
__device__ __align__(16) uint8_t g_Qq8[HQ  * SEQ * DIM];   // raw e4m3 codes
__device__ __align__(16) uint8_t g_Kq8[HKV * SEQ * DIM];
__device__ __align__(16) __half  g_Vq [HKV * SEQ * DIM];   // raw e4m3 value in fp16
__device__ float g_Qs[HQ  * 16];
__device__ float g_Ks[HKV * 8];
__device__ float g_Vs[HKV * 8];

// ---------------- helpers ----------------
static __device__ __forceinline__ unsigned short quant2e(float lo, float hi) {
    unsigned short p;
    asm("cvt.rn.satfinite.e4m3x2.f32 %0, %1, %2;" : "=h"(p) : "f"(hi), "f"(lo));
    return p;
}
static __device__ __forceinline__ uint32_t quant2h(float lo, float hi) {
    unsigned short p = quant2e(lo, hi);
    uint32_t r;
    asm("cvt.rn.f16x2.e4m3x2 %0, %1;" : "=r"(r) : "h"(p));
    return r;
}
static __device__ __forceinline__ float fast_ex2(float x) {
    float y;
    asm("ex2.approx.ftz.f32 %0, %1;" : "=f"(y) : "f"(x));
    return y;
}
static __device__ __forceinline__ void ldm4(uint32_t r[4], uint32_t addr) {
    asm volatile("ldmatrix.sync.aligned.m8n8.x4.shared.b16 {%0,%1,%2,%3}, [%4];"
                 : "=r"(r[0]), "=r"(r[1]), "=r"(r[2]), "=r"(r[3]) : "r"(addr));
}
static __device__ __forceinline__ void ldm4t(uint32_t r[4], uint32_t addr) {
    asm volatile("ldmatrix.sync.aligned.m8n8.x4.trans.shared.b16 {%0,%1,%2,%3}, [%4];"
                 : "=r"(r[0]), "=r"(r[1]), "=r"(r[2]), "=r"(r[3]) : "r"(addr));
}
// fp16 MMA (PV)
static __device__ __forceinline__ void mma16816(float c[4], const uint32_t a[4],
                                                uint32_t b0, uint32_t b1) {
    asm volatile(
        "mma.sync.aligned.m16n8k16.row.col.f32.f16.f16.f32 "
        "{%0,%1,%2,%3}, {%4,%5,%6,%7}, {%8,%9}, {%0,%1,%2,%3};"
        : "+f"(c[0]), "+f"(c[1]), "+f"(c[2]), "+f"(c[3])
        : "r"(a[0]), "r"(a[1]), "r"(a[2]), "r"(a[3]), "r"(b0), "r"(b1));
}
// fp8 MMA (QK): m16n8k32, e4m3 x e4m3 -> f32 (exact for raw e4m3 codes)
static __device__ __forceinline__ void mma16832q(float c[4], const uint32_t a[4],
                                                 uint32_t b0, uint32_t b1) {
    asm volatile(
        "mma.sync.aligned.m16n8k32.row.col.f32.e4m3.e4m3.f32 "
        "{%0,%1,%2,%3}, {%4,%5,%6,%7}, {%8,%9}, {%0,%1,%2,%3};"
        : "+f"(c[0]), "+f"(c[1]), "+f"(c[2]), "+f"(c[3])
        : "r"(a[0]), "r"(a[1]), "r"(a[2]), "r"(a[3]), "r"(b0), "r"(b1));
}
static __device__ __forceinline__ void cp16(uint32_t dst, const void* src) {
    asm volatile("cp.async.cg.shared.global [%0], [%1], 16;" :: "r"(dst), "l"(src));
}
static __device__ __forceinline__ void cp_commit() {
    asm volatile("cp.async.commit_group;" ::: "memory");
}
template <int N> static __device__ __forceinline__ void cp_wait() {
    asm volatile("cp.async.wait_group %0;" :: "n"(N) : "memory");
}

#define BFLY(x, s) { float t_ = __shfl_xor_sync(0xFFFFFFFFu, x, s); \
                     x = (lane & s) ? (t_ - x) : (x + t_); }

// FWHT of 128 elems: lane holds 4 contiguous values (idx = 4*lane + r).
// Register butterflies on bits 0,1; shuffle butterflies on bits 2..6.
static __device__ __forceinline__ void fwht4(float& v0, float& v1, float& v2, float& v3,
                                             int lane) {
    float a = v0 + v1, b = v0 - v1, c = v2 + v3, d = v2 - v3;
    v0 = a + c; v2 = a - c; v1 = b + d; v3 = b - d;
    BFLY(v0, 1)  BFLY(v1, 1)  BFLY(v2, 1)  BFLY(v3, 1)
    BFLY(v0, 2)  BFLY(v1, 2)  BFLY(v2, 2)  BFLY(v3, 2)
    BFLY(v0, 4)  BFLY(v1, 4)  BFLY(v2, 4)  BFLY(v3, 4)
    BFLY(v0, 8)  BFLY(v1, 8)  BFLY(v2, 8)  BFLY(v3, 8)
    BFLY(v0, 16) BFLY(v1, 16) BFLY(v2, 16) BFLY(v3, 16)
}

// ---------------- fused quantization: Q rot, K rot, V plain ----------------
// blocks [0,256): Q  — 128-row blocks, rotate+quant -> fp8 codes
// blocks [256,320): K — 256-row blocks, rotate+quant -> fp8 codes
// blocks [320,384): V — 256-row blocks, quant -> fp16(raw e4m3 value)
// Two-pass register FWHT (amax pass, then recompute+quantize) — no smem tile.
template <int BR>
static __device__ __forceinline__ void rotq_path(const float* __restrict__ src,
                                                 const float* __restrict__ R,
                                                 uint8_t* __restrict__ dst,
                                                 float* __restrict__ scales,
                                                 int head, int sb, int bph,
                                                 float* red) {
    const int tid = threadIdx.x, lane = tid & 31, warp = tid >> 5;
    constexpr int RW = BR / 8;
    const long base = (long)(head * SEQ + sb * BR) * DIM;

    float sg[4];
#pragma unroll
    for (int r = 0; r < 4; r++)
        sg[r] = (R[(4 * lane + r) * DIM] > 0.f) ? 1.f : -1.f;
    const float c = 0.08838834764831843f;        // 1/sqrt(128)

    const float4* s4 = reinterpret_cast<const float4*>(src + base);

    // ---- pass A: amax of |FWHT| ----
    float amax = 0.f;
#pragma unroll 4
    for (int i = 0; i < RW; i++) {
        const int row = warp * RW + i;
        float4 f = s4[row * 32 + lane];
        float v0 = f.x * sg[0], v1 = f.y * sg[1], v2 = f.z * sg[2], v3 = f.w * sg[3];
        fwht4(v0, v1, v2, v3, lane);
        amax = fmaxf(amax, fmaxf(fmaxf(fabsf(v0), fabsf(v1)), fmaxf(fabsf(v2), fabsf(v3))));
    }
#pragma unroll
    for (int o = 16; o > 0; o >>= 1) amax = fmaxf(amax, __shfl_xor_sync(~0u, amax, o));
    if (lane == 0) red[warp] = amax;
    __syncthreads();
    if (tid == 0) {
        float m = red[0];
        for (int w = 1; w < 8; w++) m = fmaxf(m, red[w]);
        red[0] = fmaxf(m * c, 1e-12f) / 448.0f;  // scale (of rotated values)
    }
    __syncthreads();
    const float scale = red[0];
    const float inv = 1.0f / scale;

    // ---- pass B: recompute FWHT, quantize, coalesced u32 store ----
    uint32_t* dq = reinterpret_cast<uint32_t*>(dst + base);
#pragma unroll 4
    for (int i = 0; i < RW; i++) {
        const int row = warp * RW + i;
        float4 f = s4[row * 32 + lane];
        float v0 = f.x * sg[0], v1 = f.y * sg[1], v2 = f.z * sg[2], v3 = f.w * sg[3];
        fwht4(v0, v1, v2, v3, lane);
        uint32_t lo = quant2e((v0 * c) * inv, (v1 * c) * inv);
        uint32_t hi = quant2e((v2 * c) * inv, (v3 * c) * inv);
        dq[row * 32 + lane] = lo | (hi << 16);
    }
    if (tid == 0) scales[head * bph + sb] = scale;
}

__global__ __launch_bounds__(256) void quant_all(const float* __restrict__ q,
                                                 const float* __restrict__ k,
                                                 const float* __restrict__ v,
                                                 const float* __restrict__ R) {
    __shared__ float red[8];
    const int b = blockIdx.x;
    const int tid = threadIdx.x, lane = tid & 31, wid = tid >> 5;

    if (b < 256) {
        rotq_path<128>(q, R, g_Qq8, g_Qs, b >> 4, b & 15, 16, red);
        return;
    }
    if (b < 320) {
        rotq_path<256>(k, R, g_Kq8, g_Ks, (b - 256) >> 3, (b - 256) & 7, 8, red);
        return;
    }

    // ---- V path: plain block quant, store raw e4m3 value widened to fp16 ----
    const int i0 = b - 320;
    const int head = i0 >> 3, vb = i0 & 7;
    const long base = (long)(head * SEQ + vb * 256) * DIM;
    const float4* s4 = reinterpret_cast<const float4*>(v + base);

    float amax = 0.f;
#pragma unroll
    for (int i = 0; i < 32; i++) {
        float4 f = s4[tid + i * 256];
        amax = fmaxf(amax, fmaxf(fmaxf(fabsf(f.x), fabsf(f.y)), fmaxf(fabsf(f.z), fabsf(f.w))));
    }
#pragma unroll
    for (int o = 16; o > 0; o >>= 1) amax = fmaxf(amax, __shfl_xor_sync(~0u, amax, o));
    if (lane == 0) red[wid] = amax;
    __syncthreads();
    if (tid == 0) {
        float m = red[0];
        for (int w = 1; w < 8; w++) m = fmaxf(m, red[w]);
        red[0] = fmaxf(m, 1e-12f) / 448.0f;
    }
    __syncthreads();
    const float scale = red[0];
    const float inv = 1.0f / scale;

    uint2* dq = reinterpret_cast<uint2*>(g_Vq + base);
#pragma unroll
    for (int i = 0; i < 32; i++) {
        int idx = tid + i * 256;
        float4 f = s4[idx];
        uint2 pk;
        pk.x = quant2h(f.x * inv, f.y * inv);
        pk.y = quant2h(f.z * inv, f.w * inv);
        dq[idx] = pk;
    }
    if (tid == 0) g_Vs[head * 8 + vb] = scale;
}

// ---------------- attention (unchanged from R10) ---------------------------
// 256 threads (8 warps), 32 Q rows/warp -> 256 Q rows/CTA, grid 8x16 = 128
// CTAs (single wave). KV tiles of 128, double-buffered, processed as 4x32-col
// chunks. Q fragments re-read from smem per k-step.
// Q/K fp8 rows: 128B data @ 144B stride. V fp16 rows: 256B data @ 272B stride.
#define SQ_   0                           // 256 * 144 = 36864
#define SK0_  36864                       // 128 * 144 = 18432
#define SK1_  55296
#define SV0_  73728                       // 128 * 272 = 34816
#define SV1_  108544
#define SMA_  143360

__global__ __launch_bounds__(256, 1) void attn_kernel(float* __restrict__ out) {
    extern __shared__ char smc[];
    const uint32_t sb = (uint32_t)__cvta_generic_to_shared(smc);
    const int qb = blockIdx.x, head = blockIdx.y;
    const int kvh = head >> 1;
    const int tid = threadIdx.x, lane = tid & 31, warp = tid >> 5;

    const uint8_t* Kg = g_Kq8 + (long)kvh * SEQ * DIM;
    const __half*  Vg = g_Vq  + (long)kvh * SEQ * DIM;

    // ---- prologue: Q block (256 rows) + tile 0 (128 rows) ----
    {
        const uint8_t* Qg = g_Qq8 + (long)(head * SEQ + qb * 256) * DIM;
#pragma unroll
        for (int i = 0; i < 8; i++) {
            int idx = tid + i * 256;            // 2048 chunks
            int row = idx >> 3, seg = idx & 7;
            cp16(sb + SQ_ + row * 144 + seg * 16, Qg + row * DIM + seg * 16);
        }
#pragma unroll
        for (int i = 0; i < 4; i++) {
            int idx = tid + i * 256;            // 1024 chunks
            int row = idx >> 3, seg = idx & 7;
            cp16(sb + SK0_ + row * 144 + seg * 16, Kg + row * DIM + seg * 16);
        }
#pragma unroll
        for (int i = 0; i < 8; i++) {
            int idx = tid + i * 256;            // 2048 chunks
            int row = idx >> 4, seg = idx & 15;
            cp16(sb + SV0_ + row * 272 + seg * 16, Vg + row * DIM + seg * 8);
        }
        cp_commit();
    }
    cp_wait<0>();
    __syncthreads();

    float oacc[2][16][4];
#pragma unroll
    for (int mf = 0; mf < 2; mf++)
#pragma unroll
        for (int n = 0; n < 16; n++)
#pragma unroll
            for (int c = 0; c < 4; c++) oacc[mf][n][c] = 0.f;
    float denom[4] = {0.f, 0.f, 0.f, 0.f};

    // Q scale: rows 0-127 of CTA use block qb*2, rows 128-255 use qb*2+1
    const float sq = g_Qs[head * 16 + qb * 2 + (warp >> 2)];
    const float RS_LOG2E = 0.08838834764831843f * 1.4426950408889634f;

    // hoisted per-thread addresses
    const uint32_t qbase = sb + SQ_ + (uint32_t)(warp * 32 + (lane & 15)) * 144 +
                           (uint32_t)((lane >> 4) * 16);
    const uint32_t kR = (uint32_t)(((lane & 7) + ((lane >> 4) << 3)) * 144 +
                                   ((lane >> 3) & 1) * 16);
    const uint32_t vR = (uint32_t)(((lane & 7) + (((lane >> 3) & 1) << 3)) * 272 +
                                   ((lane >> 4) * 16));

    for (int t = 0; t < 16; t++) {
        const int p = t & 1;
        const uint32_t kb   = sb + SK0_ + p * 18432;
        const uint32_t vbuf = sb + SV0_ + p * 34816;

        // ---- issue async loads for tile t+1 into the other buffer ----
        if (t < 15) {
            const uint32_t kb2 = sb + SK0_ + (1 - p) * 18432;
            const uint32_t vb2 = sb + SV0_ + (1 - p) * 34816;
            const uint8_t* Kt = Kg + (long)(t + 1) * 128 * DIM;
            const __half*  Vt = Vg + (long)(t + 1) * 128 * DIM;
#pragma unroll
            for (int i = 0; i < 4; i++) {
                int idx = tid + i * 256;
                int row = idx >> 3, seg = idx & 7;
                cp16(kb2 + row * 144 + seg * 16, Kt + row * DIM + seg * 16);
            }
#pragma unroll
            for (int i = 0; i < 8; i++) {
                int idx = tid + i * 256;
                int row = idx >> 4, seg = idx & 15;
                cp16(vb2 + row * 272 + seg * 16, Vt + row * DIM + seg * 8);
            }
            cp_commit();
        }

        const float m  = sq * g_Ks[kvh * 8 + (t >> 1)] * RS_LOG2E;
        const float sv = g_Vs[kvh * 8 + (t >> 1)];

        // ---- process tile as four 32-kv-col chunks ----
#pragma unroll
        for (int ch = 0; ch < 4; ch++) {
            // S chunk: 32 Q rows x 32 KV cols (fp8, exact)
            float sacc[2][4][4];
#pragma unroll
            for (int mf = 0; mf < 2; mf++)
#pragma unroll
                for (int j = 0; j < 4; j++)
#pragma unroll
                    for (int c = 0; c < 4; c++) sacc[mf][j][c] = 0.f;

#pragma unroll
            for (int kk = 0; kk < 4; kk++) {
                uint32_t q0[4], q1[4];
                ldm4(q0, qbase + kk * 32);              // mf0 rows
                ldm4(q1, qbase + 16 * 144 + kk * 32);   // mf1 rows
#pragma unroll
                for (int jp = 0; jp < 2; jp++) {
                    uint32_t b[4];
                    ldm4(b, kb + kR + (ch * 32 + jp * 16) * 144 + kk * 32);
                    mma16832q(sacc[0][2 * jp],     q0, b[0], b[1]);
                    mma16832q(sacc[0][2 * jp + 1], q0, b[2], b[3]);
                    mma16832q(sacc[1][2 * jp],     q1, b[0], b[1]);
                    mma16832q(sacc[1][2 * jp + 1], q1, b[2], b[3]);
                }
            }

            // softmax (no-max; constant -6 shift cancels), fold V scale
            uint32_t pf[2][4][2];
#pragma unroll
            for (int mf = 0; mf < 2; mf++) {
#pragma unroll
                for (int j = 0; j < 4; j++) {
                    float e0 = fast_ex2(fmaf(sacc[mf][j][0], m, -6.f));
                    float e1 = fast_ex2(fmaf(sacc[mf][j][1], m, -6.f));
                    float e2 = fast_ex2(fmaf(sacc[mf][j][2], m, -6.f));
                    float e3 = fast_ex2(fmaf(sacc[mf][j][3], m, -6.f));
                    denom[2 * mf]     += e0 + e1;
                    denom[2 * mf + 1] += e2 + e3;
                    __half2 h01 = __floats2half2_rn(e0 * sv, e1 * sv);
                    __half2 h23 = __floats2half2_rn(e2 * sv, e3 * sv);
                    pf[mf][j][0] = *reinterpret_cast<uint32_t*>(&h01);
                    pf[mf][j][1] = *reinterpret_cast<uint32_t*>(&h23);
                }
            }

            // O += P . Vraw (fp16): k = 32 (2 k16 steps)
#pragma unroll
            for (int kk = 0; kk < 2; kk++) {
                uint32_t a0[4] = {pf[0][2 * kk][0], pf[0][2 * kk][1],
                                  pf[0][2 * kk + 1][0], pf[0][2 * kk + 1][1]};
                uint32_t a1[4] = {pf[1][2 * kk][0], pf[1][2 * kk][1],
                                  pf[1][2 * kk + 1][0], pf[1][2 * kk + 1][1]};
#pragma unroll
                for (int dp = 0; dp < 8; dp++) {
                    uint32_t b[4];
                    ldm4t(b, vbuf + vR + (ch * 32 + kk * 16) * 272 + dp * 32);
                    mma16816(oacc[0][2 * dp],     a0, b[0], b[1]);
                    mma16816(oacc[0][2 * dp + 1], a0, b[2], b[3]);
                    mma16816(oacc[1][2 * dp],     a1, b[0], b[1]);
                    mma16816(oacc[1][2 * dp + 1], a1, b[2], b[3]);
                }
            }
        }

        if (t < 15) {
            cp_wait<0>();
            __syncthreads();
        }
    }

    // ---- epilogue ----
#pragma unroll
    for (int d = 0; d < 4; d++) {
        denom[d] += __shfl_xor_sync(~0u, denom[d], 1);
        denom[d] += __shfl_xor_sync(~0u, denom[d], 2);
        denom[d] = 1.0f / denom[d];
    }

    float* ob = out + (long)head * SEQ * DIM;
#pragma unroll
    for (int mf = 0; mf < 2; mf++) {
        const int row0 = qb * 256 + warp * 32 + mf * 16 + (lane >> 2);
        const float inv0 = denom[2 * mf], inv1 = denom[2 * mf + 1];
#pragma unroll
        for (int dt = 0; dt < 16; dt++) {
            int col = dt * 8 + (lane & 3) * 2;
            ob[(long)row0 * DIM + col]           = oacc[mf][dt][0] * inv0;
            ob[(long)row0 * DIM + col + 1]       = oacc[mf][dt][1] * inv0;
            ob[(long)(row0 + 8) * DIM + col]     = oacc[mf][dt][2] * inv1;
            ob[(long)(row0 + 8) * DIM + col + 1] = oacc[mf][dt][3] * inv1;
        }
    }
}

// ---------------- host ----------------
extern "C" void kernel_launch(void* const* d_in, const int* in_sizes, int n_in,
                              void* d_out, int out_size) {
    (void)in_sizes; (void)n_in; (void)out_size;
    const float* q = (const float*)d_in[0];
    const float* k = (const float*)d_in[1];
    const float* v = (const float*)d_in[2];
    const float* R = (const float*)d_in[3];
    float* out = (float*)d_out;

    cudaFuncSetAttribute((const void*)attn_kernel,
                         cudaFuncAttributeMaxDynamicSharedMemorySize, SMA_);

    quant_all<<<384, 256>>>(q, k, v, R);
    attn_kernel<<<dim3(8, HQ), 256, SMA_>>>(out);
}

// round 14
// speedup vs baseline: 1.0308x; 1.0308x over previous
#include <cuda_runtime.h>
#include <cuda_fp16.h>
#include <cstdint>

#define HQ   16
#define HKV  8
#define SEQ  2048
#define DIM  128

// ---------------- device scratch ----------------
__device__ __align__(16) uint8_t g_Kq8[HKV * SEQ * DIM];   // raw e4m3 codes
__device__ __align__(16) __half  g_Vq [HKV * SEQ * DIM];   // raw e4m3 value in fp16
__device__ float g_Ks[HKV * 8];
__device__ float g_Vs[HKV * 8];

// ---------------- helpers ----------------
static __device__ __forceinline__ unsigned short quant2e(float lo, float hi) {
    unsigned short p;
    asm("cvt.rn.satfinite.e4m3x2.f32 %0, %1, %2;" : "=h"(p) : "f"(hi), "f"(lo));
    return p;
}
static __device__ __forceinline__ uint32_t quant2h(float lo, float hi) {
    unsigned short p = quant2e(lo, hi);
    uint32_t r;
    asm("cvt.rn.f16x2.e4m3x2 %0, %1;" : "=r"(r) : "h"(p));
    return r;
}
static __device__ __forceinline__ float fast_ex2(float x) {
    float y;
    asm("ex2.approx.ftz.f32 %0, %1;" : "=f"(y) : "f"(x));
    return y;
}
static __device__ __forceinline__ void ldm4(uint32_t r[4], uint32_t addr) {
    asm volatile("ldmatrix.sync.aligned.m8n8.x4.shared.b16 {%0,%1,%2,%3}, [%4];"
                 : "=r"(r[0]), "=r"(r[1]), "=r"(r[2]), "=r"(r[3]) : "r"(addr));
}
static __device__ __forceinline__ void ldm4t(uint32_t r[4], uint32_t addr) {
    asm volatile("ldmatrix.sync.aligned.m8n8.x4.trans.shared.b16 {%0,%1,%2,%3}, [%4];"
                 : "=r"(r[0]), "=r"(r[1]), "=r"(r[2]), "=r"(r[3]) : "r"(addr));
}
// fp16 MMA (PV)
static __device__ __forceinline__ void mma16816(float c[4], const uint32_t a[4],
                                                uint32_t b0, uint32_t b1) {
    asm volatile(
        "mma.sync.aligned.m16n8k16.row.col.f32.f16.f16.f32 "
        "{%0,%1,%2,%3}, {%4,%5,%6,%7}, {%8,%9}, {%0,%1,%2,%3};"
        : "+f"(c[0]), "+f"(c[1]), "+f"(c[2]), "+f"(c[3])
        : "r"(a[0]), "r"(a[1]), "r"(a[2]), "r"(a[3]), "r"(b0), "r"(b1));
}
// fp8 MMA (QK): m16n8k32, e4m3 x e4m3 -> f32 (exact for raw e4m3 codes)
static __device__ __forceinline__ void mma16832q(float c[4], const uint32_t a[4],
                                                 uint32_t b0, uint32_t b1) {
    asm volatile(
        "mma.sync.aligned.m16n8k32.row.col.f32.e4m3.e4m3.f32 "
        "{%0,%1,%2,%3}, {%4,%5,%6,%7}, {%8,%9}, {%0,%1,%2,%3};"
        : "+f"(c[0]), "+f"(c[1]), "+f"(c[2]), "+f"(c[3])
        : "r"(a[0]), "r"(a[1]), "r"(a[2]), "r"(a[3]), "r"(b0), "r"(b1));
}
static __device__ __forceinline__ void cp16(uint32_t dst, const void* src) {
    asm volatile("cp.async.cg.shared.global [%0], [%1], 16;" :: "r"(dst), "l"(src));
}
static __device__ __forceinline__ void cp_commit() {
    asm volatile("cp.async.commit_group;" ::: "memory");
}
template <int N> static __device__ __forceinline__ void cp_wait() {
    asm volatile("cp.async.wait_group %0;" :: "n"(N) : "memory");
}

#define BFLY(x, s) { float t_ = __shfl_xor_sync(0xFFFFFFFFu, x, s); \
                     x = (lane & s) ? (t_ - x) : (x + t_); }

// FWHT of 128 elems: lane holds 4 contiguous values (idx = 4*lane + r).
// Register butterflies on bits 0,1; shuffle butterflies on bits 2..6.
static __device__ __forceinline__ void fwht4(float& v0, float& v1, float& v2, float& v3,
                                             int lane) {
    float a = v0 + v1, b = v0 - v1, c = v2 + v3, d = v2 - v3;
    v0 = a + c; v2 = a - c; v1 = b + d; v3 = b - d;
    BFLY(v0, 1)  BFLY(v1, 1)  BFLY(v2, 1)  BFLY(v3, 1)
    BFLY(v0, 2)  BFLY(v1, 2)  BFLY(v2, 2)  BFLY(v3, 2)
    BFLY(v0, 4)  BFLY(v1, 4)  BFLY(v2, 4)  BFLY(v3, 4)
    BFLY(v0, 8)  BFLY(v1, 8)  BFLY(v2, 8)  BFLY(v3, 8)
    BFLY(v0, 16) BFLY(v1, 16) BFLY(v2, 16) BFLY(v3, 16)
}

// ---------------- K + V quantization (Q is fused into attention) -----------
// 512 threads. blocks [0,64): K — 256-row blocks, rotate+quant -> fp8 codes.
// blocks [64,128): V — 256-row blocks, quant -> fp16(raw e4m3 value).
__global__ __launch_bounds__(512) void quant_kv(const float* __restrict__ k,
                                                const float* __restrict__ v,
                                                const float* __restrict__ R) {
    __shared__ float red[16];
    const int b = blockIdx.x;
    const int tid = threadIdx.x, lane = tid & 31, warp = tid >> 5;

    if (b < 64) {
        // ---- K rotate + quant (two-pass register FWHT) ----
        const int head = b >> 3, sb = b & 7;
        const long base = (long)(head * SEQ + sb * 256) * DIM;
        float sg[4];
#pragma unroll
        for (int r = 0; r < 4; r++)
            sg[r] = (R[(4 * lane + r) * DIM] > 0.f) ? 1.f : -1.f;
        const float c = 0.08838834764831843f;    // 1/sqrt(128)
        const float4* s4 = reinterpret_cast<const float4*>(k + base);

        float amax = 0.f;
#pragma unroll 4
        for (int i = 0; i < 16; i++) {
            const int row = warp * 16 + i;
            float4 f = s4[row * 32 + lane];
            float v0 = f.x * sg[0], v1 = f.y * sg[1], v2 = f.z * sg[2], v3 = f.w * sg[3];
            fwht4(v0, v1, v2, v3, lane);
            amax = fmaxf(amax, fmaxf(fmaxf(fabsf(v0), fabsf(v1)), fmaxf(fabsf(v2), fabsf(v3))));
        }
#pragma unroll
        for (int o = 16; o > 0; o >>= 1) amax = fmaxf(amax, __shfl_xor_sync(~0u, amax, o));
        if (lane == 0) red[warp] = amax;
        __syncthreads();
        if (tid == 0) {
            float m = red[0];
            for (int w = 1; w < 16; w++) m = fmaxf(m, red[w]);
            red[0] = fmaxf(m * c, 1e-12f) / 448.0f;
        }
        __syncthreads();
        const float scale = red[0];
        const float inv = 1.0f / scale;

        uint32_t* dq = reinterpret_cast<uint32_t*>(g_Kq8 + base);
#pragma unroll 4
        for (int i = 0; i < 16; i++) {
            const int row = warp * 16 + i;
            float4 f = s4[row * 32 + lane];
            float v0 = f.x * sg[0], v1 = f.y * sg[1], v2 = f.z * sg[2], v3 = f.w * sg[3];
            fwht4(v0, v1, v2, v3, lane);
            uint32_t lo = quant2e((v0 * c) * inv, (v1 * c) * inv);
            uint32_t hi = quant2e((v2 * c) * inv, (v3 * c) * inv);
            dq[row * 32 + lane] = lo | (hi << 16);
        }
        if (tid == 0) g_Ks[head * 8 + sb] = scale;
        return;
    }

    // ---- V plain block quant, store raw e4m3 value widened to fp16 ----
    const int i0 = b - 64;
    const int head = i0 >> 3, vb = i0 & 7;
    const long base = (long)(head * SEQ + vb * 256) * DIM;
    const float4* s4 = reinterpret_cast<const float4*>(v + base);

    float amax = 0.f;
#pragma unroll
    for (int i = 0; i < 16; i++) {
        float4 f = s4[tid + i * 512];
        amax = fmaxf(amax, fmaxf(fmaxf(fabsf(f.x), fabsf(f.y)), fmaxf(fabsf(f.z), fabsf(f.w))));
    }
#pragma unroll
    for (int o = 16; o > 0; o >>= 1) amax = fmaxf(amax, __shfl_xor_sync(~0u, amax, o));
    if (lane == 0) red[warp] = amax;
    __syncthreads();
    if (tid == 0) {
        float m = red[0];
        for (int w = 1; w < 16; w++) m = fmaxf(m, red[w]);
        red[0] = fmaxf(m, 1e-12f) / 448.0f;
    }
    __syncthreads();
    const float scale = red[0];
    const float inv = 1.0f / scale;

    uint2* dq = reinterpret_cast<uint2*>(g_Vq + base);
#pragma unroll
    for (int i = 0; i < 16; i++) {
        int idx = tid + i * 512;
        float4 f = s4[idx];
        uint2 pk;
        pk.x = quant2h(f.x * inv, f.y * inv);
        pk.y = quant2h(f.z * inv, f.w * inv);
        dq[idx] = pk;
    }
    if (tid == 0) g_Vs[head * 8 + vb] = scale;
}

// ---------------- attention (Q rotate+quant fused into prologue) -----------
// 256 threads (8 warps), 32 Q rows/warp -> 256 Q rows/CTA, grid 8x16 = 128
// CTAs (single wave). KV tiles of 128, double-buffered, 4x32-col chunks.
// Q/K fp8 rows: 128B data @ 144B stride. V fp16 rows: 256B data @ 272B stride.
#define SQ_   0                           // 256 * 144 = 36864
#define SK0_  36864                       // 128 * 144 = 18432
#define SK1_  55296
#define SV0_  73728                       // 128 * 272 = 34816
#define SV1_  108544
#define SMA_  143424                      // + 64B for reduce scratch
#define SRED_ 143360

__global__ __launch_bounds__(256, 1) void attn_kernel(const float* __restrict__ qg,
                                                      const float* __restrict__ R,
                                                      float* __restrict__ out) {
    extern __shared__ char smc[];
    const uint32_t sb = (uint32_t)__cvta_generic_to_shared(smc);
    const int qb = blockIdx.x, head = blockIdx.y;
    const int kvh = head >> 1;
    const int tid = threadIdx.x, lane = tid & 31, warp = tid >> 5;
    float* red = reinterpret_cast<float*>(smc + SRED_);

    const uint8_t* Kg = g_Kq8 + (long)kvh * SEQ * DIM;
    const __half*  Vg = g_Vq  + (long)kvh * SEQ * DIM;

    // ---- prologue 1: issue K/V tile 0 cp.asyncs ----
#pragma unroll
    for (int i = 0; i < 4; i++) {
        int idx = tid + i * 256;                // 1024 chunks
        int row = idx >> 3, seg = idx & 7;
        cp16(sb + SK0_ + row * 144 + seg * 16, Kg + row * DIM + seg * 16);
    }
#pragma unroll
    for (int i = 0; i < 8; i++) {
        int idx = tid + i * 256;                // 2048 chunks
        int row = idx >> 4, seg = idx & 15;
        cp16(sb + SV0_ + row * 272 + seg * 16, Vg + row * DIM + seg * 8);
    }
    cp_commit();

    // ---- prologue 2: Q rotate + quantize into smem (CTA-local scales) ----
    // warp w owns rows w*32..w*32+31; warps 0-3 = scale half 0, 4-7 = half 1.
    float qscale;
    {
        const float4* s4 = reinterpret_cast<const float4*>(
            qg + (long)(head * SEQ + qb * 256) * DIM);
        float sg[4];
#pragma unroll
        for (int r = 0; r < 4; r++)
            sg[r] = (R[(4 * lane + r) * DIM] > 0.f) ? 1.f : -1.f;
        const float c = 0.08838834764831843f;   // 1/sqrt(128)

        float amax = 0.f;
#pragma unroll 4
        for (int i = 0; i < 32; i++) {
            const int row = warp * 32 + i;
            float4 f = s4[row * 32 + lane];
            float v0 = f.x * sg[0], v1 = f.y * sg[1], v2 = f.z * sg[2], v3 = f.w * sg[3];
            fwht4(v0, v1, v2, v3, lane);
            amax = fmaxf(amax, fmaxf(fmaxf(fabsf(v0), fabsf(v1)), fmaxf(fabsf(v2), fabsf(v3))));
        }
#pragma unroll
        for (int o = 16; o > 0; o >>= 1) amax = fmaxf(amax, __shfl_xor_sync(~0u, amax, o));
        if (lane == 0) red[warp] = amax;
        __syncthreads();
        {
            const int h0 = (warp >> 2) * 4;
            float m = fmaxf(fmaxf(red[h0], red[h0 + 1]), fmaxf(red[h0 + 2], red[h0 + 3]));
            qscale = fmaxf(m * c, 1e-12f) / 448.0f;
        }
        const float inv = 1.0f / qscale;

#pragma unroll 4
        for (int i = 0; i < 32; i++) {
            const int row = warp * 32 + i;
            float4 f = s4[row * 32 + lane];
            float v0 = f.x * sg[0], v1 = f.y * sg[1], v2 = f.z * sg[2], v3 = f.w * sg[3];
            fwht4(v0, v1, v2, v3, lane);
            uint32_t lo = quant2e((v0 * c) * inv, (v1 * c) * inv);
            uint32_t hi = quant2e((v2 * c) * inv, (v3 * c) * inv);
            *reinterpret_cast<uint32_t*>(smc + SQ_ + row * 144 + lane * 4) = lo | (hi << 16);
        }
    }

    cp_wait<0>();
    __syncthreads();

    float oacc[2][16][4];
#pragma unroll
    for (int mf = 0; mf < 2; mf++)
#pragma unroll
        for (int n = 0; n < 16; n++)
#pragma unroll
            for (int c = 0; c < 4; c++) oacc[mf][n][c] = 0.f;
    float denom[4] = {0.f, 0.f, 0.f, 0.f};

    const float RS_LOG2E = 0.08838834764831843f * 1.4426950408889634f;

    // hoisted per-thread addresses
    const uint32_t qbase = sb + SQ_ + (uint32_t)(warp * 32 + (lane & 15)) * 144 +
                           (uint32_t)((lane >> 4) * 16);
    const uint32_t kR = (uint32_t)(((lane & 7) + ((lane >> 4) << 3)) * 144 +
                                   ((lane >> 3) & 1) * 16);
    const uint32_t vR = (uint32_t)(((lane & 7) + (((lane >> 3) & 1) << 3)) * 272 +
                                   ((lane >> 4) * 16));

    for (int t = 0; t < 16; t++) {
        const int p = t & 1;
        const uint32_t kb   = sb + SK0_ + p * 18432;
        const uint32_t vbuf = sb + SV0_ + p * 34816;

        // ---- issue async loads for tile t+1 into the other buffer ----
        if (t < 15) {
            const uint32_t kb2 = sb + SK0_ + (1 - p) * 18432;
            const uint32_t vb2 = sb + SV0_ + (1 - p) * 34816;
            const uint8_t* Kt = Kg + (long)(t + 1) * 128 * DIM;
            const __half*  Vt = Vg + (long)(t + 1) * 128 * DIM;
#pragma unroll
            for (int i = 0; i < 4; i++) {
                int idx = tid + i * 256;
                int row = idx >> 3, seg = idx & 7;
                cp16(kb2 + row * 144 + seg * 16, Kt + row * DIM + seg * 16);
            }
#pragma unroll
            for (int i = 0; i < 8; i++) {
                int idx = tid + i * 256;
                int row = idx >> 4, seg = idx & 15;
                cp16(vb2 + row * 272 + seg * 16, Vt + row * DIM + seg * 8);
            }
            cp_commit();
        }

        const float m  = qscale * g_Ks[kvh * 8 + (t >> 1)] * RS_LOG2E;
        const float sv = g_Vs[kvh * 8 + (t >> 1)];

        // ---- process tile as four 32-kv-col chunks ----
#pragma unroll
        for (int ch = 0; ch < 4; ch++) {
            // S chunk: 32 Q rows x 32 KV cols (fp8, exact)
            float sacc[2][4][4];
#pragma unroll
            for (int mf = 0; mf < 2; mf++)
#pragma unroll
                for (int j = 0; j < 4; j++)
#pragma unroll
                    for (int c = 0; c < 4; c++) sacc[mf][j][c] = 0.f;

#pragma unroll
            for (int kk = 0; kk < 4; kk++) {
                uint32_t q0[4], q1[4];
                ldm4(q0, qbase + kk * 32);              // mf0 rows
                ldm4(q1, qbase + 16 * 144 + kk * 32);   // mf1 rows
#pragma unroll
                for (int jp = 0; jp < 2; jp++) {
                    uint32_t b[4];
                    ldm4(b, kb + kR + (ch * 32 + jp * 16) * 144 + kk * 32);
                    mma16832q(sacc[0][2 * jp],     q0, b[0], b[1]);
                    mma16832q(sacc[0][2 * jp + 1], q0, b[2], b[3]);
                    mma16832q(sacc[1][2 * jp],     q1, b[0], b[1]);
                    mma16832q(sacc[1][2 * jp + 1], q1, b[2], b[3]);
                }
            }

            // softmax (no-max; constant -6 shift cancels), fold V scale
            uint32_t pf[2][4][2];
#pragma unroll
            for (int mf = 0; mf < 2; mf++) {
#pragma unroll
                for (int j = 0; j < 4; j++) {
                    float e0 = fast_ex2(fmaf(sacc[mf][j][0], m, -6.f));
                    float e1 = fast_ex2(fmaf(sacc[mf][j][1], m, -6.f));
                    float e2 = fast_ex2(fmaf(sacc[mf][j][2], m, -6.f));
                    float e3 = fast_ex2(fmaf(sacc[mf][j][3], m, -6.f));
                    denom[2 * mf]     += e0 + e1;
                    denom[2 * mf + 1] += e2 + e3;
                    __half2 h01 = __floats2half2_rn(e0 * sv, e1 * sv);
                    __half2 h23 = __floats2half2_rn(e2 * sv, e3 * sv);
                    pf[mf][j][0] = *reinterpret_cast<uint32_t*>(&h01);
                    pf[mf][j][1] = *reinterpret_cast<uint32_t*>(&h23);
                }
            }

            // O += P . Vraw (fp16): k = 32 (2 k16 steps)
#pragma unroll
            for (int kk = 0; kk < 2; kk++) {
                uint32_t a0[4] = {pf[0][2 * kk][0], pf[0][2 * kk][1],
                                  pf[0][2 * kk + 1][0], pf[0][2 * kk + 1][1]};
                uint32_t a1[4] = {pf[1][2 * kk][0], pf[1][2 * kk][1],
                                  pf[1][2 * kk + 1][0], pf[1][2 * kk + 1][1]};
#pragma unroll
                for (int dp = 0; dp < 8; dp++) {
                    uint32_t b[4];
                    ldm4t(b, vbuf + vR + (ch * 32 + kk * 16) * 272 + dp * 32);
                    mma16816(oacc[0][2 * dp],     a0, b[0], b[1]);
                    mma16816(oacc[0][2 * dp + 1], a0, b[2], b[3]);
                    mma16816(oacc[1][2 * dp],     a1, b[0], b[1]);
                    mma16816(oacc[1][2 * dp + 1], a1, b[2], b[3]);
                }
            }
        }

        if (t < 15) {
            cp_wait<0>();
            __syncthreads();
        }
    }

    // ---- epilogue ----
#pragma unroll
    for (int d = 0; d < 4; d++) {
        denom[d] += __shfl_xor_sync(~0u, denom[d], 1);
        denom[d] += __shfl_xor_sync(~0u, denom[d], 2);
        denom[d] = 1.0f / denom[d];
    }

    float* ob = out + (long)head * SEQ * DIM;
#pragma unroll
    for (int mf = 0; mf < 2; mf++) {
        const int row0 = qb * 256 + warp * 32 + mf * 16 + (lane >> 2);
        const float inv0 = denom[2 * mf], inv1 = denom[2 * mf + 1];
#pragma unroll
        for (int dt = 0; dt < 16; dt++) {
            int col = dt * 8 + (lane & 3) * 2;
            ob[(long)row0 * DIM + col]           = oacc[mf][dt][0] * inv0;
            ob[(long)row0 * DIM + col + 1]       = oacc[mf][dt][1] * inv0;
            ob[(long)(row0 + 8) * DIM + col]     = oacc[mf][dt][2] * inv1;
            ob[(long)(row0 + 8) * DIM + col + 1] = oacc[mf][dt][3] * inv1;
        }
    }
}

// ---------------- host ----------------
extern "C" void kernel_launch(void* const* d_in, const int* in_sizes, int n_in,
                              void* d_out, int out_size) {
    (void)in_sizes; (void)n_in; (void)out_size;
    const float* q = (const float*)d_in[0];
    const float* k = (const float*)d_in[1];
    const float* v = (const float*)d_in[2];
    const float* R = (const float*)d_in[3];
    float* out = (float*)d_out;

    cudaFuncSetAttribute((const void*)attn_kernel,
                         cudaFuncAttributeMaxDynamicSharedMemorySize, SMA_);

    quant_kv<<<128, 512>>>(k, v, R);
    attn_kernel<<<dim3(8, HQ), 256, SMA_>>>(q, R, out);
}

// round 15
// speedup vs baseline: 1.0765x; 1.0444x over previous
#include <cuda_runtime.h>
#include <cuda_fp16.h>
#include <cstdint>

#define HQ   16
#define HKV  8
#define SEQ  2048
#define DIM  128

// ---------------- device scratch ----------------
__device__ __align__(16) uint8_t g_Kq8[HKV * SEQ * DIM];   // raw e4m3 codes
__device__ __align__(16) __half  g_Vq [HKV * SEQ * DIM];   // raw e4m3 value in fp16
__device__ float g_Ks[HKV * 8];
__device__ float g_Vs[HKV * 8];

// ---------------- helpers ----------------
static __device__ __forceinline__ unsigned short quant2e(float lo, float hi) {
    unsigned short p;
    asm("cvt.rn.satfinite.e4m3x2.f32 %0, %1, %2;" : "=h"(p) : "f"(hi), "f"(lo));
    return p;
}
static __device__ __forceinline__ uint32_t quant2h(float lo, float hi) {
    unsigned short p = quant2e(lo, hi);
    uint32_t r;
    asm("cvt.rn.f16x2.e4m3x2 %0, %1;" : "=r"(r) : "h"(p));
    return r;
}
static __device__ __forceinline__ float fast_ex2(float x) {
    float y;
    asm("ex2.approx.ftz.f32 %0, %1;" : "=f"(y) : "f"(x));
    return y;
}
static __device__ __forceinline__ void ldm4(uint32_t r[4], uint32_t addr) {
    asm volatile("ldmatrix.sync.aligned.m8n8.x4.shared.b16 {%0,%1,%2,%3}, [%4];"
                 : "=r"(r[0]), "=r"(r[1]), "=r"(r[2]), "=r"(r[3]) : "r"(addr));
}
static __device__ __forceinline__ void ldm4t(uint32_t r[4], uint32_t addr) {
    asm volatile("ldmatrix.sync.aligned.m8n8.x4.trans.shared.b16 {%0,%1,%2,%3}, [%4];"
                 : "=r"(r[0]), "=r"(r[1]), "=r"(r[2]), "=r"(r[3]) : "r"(addr));
}
// fp16 MMA (PV)
static __device__ __forceinline__ void mma16816(float c[4], const uint32_t a[4],
                                                uint32_t b0, uint32_t b1) {
    asm volatile(
        "mma.sync.aligned.m16n8k16.row.col.f32.f16.f16.f32 "
        "{%0,%1,%2,%3}, {%4,%5,%6,%7}, {%8,%9}, {%0,%1,%2,%3};"
        : "+f"(c[0]), "+f"(c[1]), "+f"(c[2]), "+f"(c[3])
        : "r"(a[0]), "r"(a[1]), "r"(a[2]), "r"(a[3]), "r"(b0), "r"(b1));
}
// fp8 MMA (QK): m16n8k32, e4m3 x e4m3 -> f32 (exact for raw e4m3 codes)
static __device__ __forceinline__ void mma16832q(float c[4], const uint32_t a[4],
                                                 uint32_t b0, uint32_t b1) {
    asm volatile(
        "mma.sync.aligned.m16n8k32.row.col.f32.e4m3.e4m3.f32 "
        "{%0,%1,%2,%3}, {%4,%5,%6,%7}, {%8,%9}, {%0,%1,%2,%3};"
        : "+f"(c[0]), "+f"(c[1]), "+f"(c[2]), "+f"(c[3])
        : "r"(a[0]), "r"(a[1]), "r"(a[2]), "r"(a[3]), "r"(b0), "r"(b1));
}
static __device__ __forceinline__ void cp16(uint32_t dst, const void* src) {
    asm volatile("cp.async.cg.shared.global [%0], [%1], 16;" :: "r"(dst), "l"(src));
}
static __device__ __forceinline__ void cp_commit() {
    asm volatile("cp.async.commit_group;" ::: "memory");
}
template <int N> static __device__ __forceinline__ void cp_wait() {
    asm volatile("cp.async.wait_group %0;" :: "n"(N) : "memory");
}

#define BFLY(x, s) { float t_ = __shfl_xor_sync(0xFFFFFFFFu, x, s); \
                     x = (lane & s) ? (t_ - x) : (x + t_); }

// FWHT of 128 elems: lane holds 4 contiguous values (idx = 4*lane + r).
// Register butterflies on bits 0,1; shuffle butterflies on bits 2..6.
static __device__ __forceinline__ void fwht4(float& v0, float& v1, float& v2, float& v3,
                                             int lane) {
    float a = v0 + v1, b = v0 - v1, c = v2 + v3, d = v2 - v3;
    v0 = a + c; v2 = a - c; v1 = b + d; v3 = b - d;
    BFLY(v0, 1)  BFLY(v1, 1)  BFLY(v2, 1)  BFLY(v3, 1)
    BFLY(v0, 2)  BFLY(v1, 2)  BFLY(v2, 2)  BFLY(v3, 2)
    BFLY(v0, 4)  BFLY(v1, 4)  BFLY(v2, 4)  BFLY(v3, 4)
    BFLY(v0, 8)  BFLY(v1, 8)  BFLY(v2, 8)  BFLY(v3, 8)
    BFLY(v0, 16) BFLY(v1, 16) BFLY(v2, 16) BFLY(v3, 16)
}

// ---------------- K + V quantization (Q is fused into attention) -----------
// 512 threads. blocks [0,64): K — 256-row blocks, rotate+quant -> fp8 codes.
// blocks [64,128): V — 256-row blocks, quant -> fp16(raw e4m3 value).
// One pass: FWHT results held in registers while amax reduces.
__global__ __launch_bounds__(512) void quant_kv(const float* __restrict__ k,
                                                const float* __restrict__ v,
                                                const float* __restrict__ R) {
    __shared__ float red[16];
    const int b = blockIdx.x;
    const int tid = threadIdx.x, lane = tid & 31, warp = tid >> 5;

    if (b < 64) {
        // ---- K rotate + quant (one-pass register FWHT) ----
        const int head = b >> 3, sb = b & 7;
        const long base = (long)(head * SEQ + sb * 256) * DIM;
        float sg[4];
#pragma unroll
        for (int r = 0; r < 4; r++)
            sg[r] = (R[(4 * lane + r) * DIM] > 0.f) ? 1.f : -1.f;
        const float c = 0.08838834764831843f;    // 1/sqrt(128)
        const float4* s4 = reinterpret_cast<const float4*>(k + base);

        float w0[16], w1[16], w2[16], w3[16];
        float amax = 0.f;
#pragma unroll
        for (int i = 0; i < 16; i++) {
            const int row = warp * 16 + i;
            float4 f = s4[row * 32 + lane];
            float v0 = f.x * sg[0], v1 = f.y * sg[1], v2 = f.z * sg[2], v3 = f.w * sg[3];
            fwht4(v0, v1, v2, v3, lane);
            w0[i] = v0; w1[i] = v1; w2[i] = v2; w3[i] = v3;
            amax = fmaxf(amax, fmaxf(fmaxf(fabsf(v0), fabsf(v1)), fmaxf(fabsf(v2), fabsf(v3))));
        }
#pragma unroll
        for (int o = 16; o > 0; o >>= 1) amax = fmaxf(amax, __shfl_xor_sync(~0u, amax, o));
        if (lane == 0) red[warp] = amax;
        __syncthreads();
        if (tid == 0) {
            float m = red[0];
            for (int w = 1; w < 16; w++) m = fmaxf(m, red[w]);
            red[0] = fmaxf(m * c, 1e-12f) / 448.0f;
        }
        __syncthreads();
        const float scale = red[0];
        const float inv = 1.0f / scale;

        uint32_t* dq = reinterpret_cast<uint32_t*>(g_Kq8 + base);
#pragma unroll
        for (int i = 0; i < 16; i++) {
            const int row = warp * 16 + i;
            uint32_t lo = quant2e((w0[i] * c) * inv, (w1[i] * c) * inv);
            uint32_t hi = quant2e((w2[i] * c) * inv, (w3[i] * c) * inv);
            dq[row * 32 + lane] = lo | (hi << 16);
        }
        if (tid == 0) g_Ks[head * 8 + sb] = scale;
        return;
    }

    // ---- V plain block quant (one pass, values held in registers) ----
    const int i0 = b - 64;
    const int head = i0 >> 3, vb = i0 & 7;
    const long base = (long)(head * SEQ + vb * 256) * DIM;
    const float4* s4 = reinterpret_cast<const float4*>(v + base);

    float4 f[16];
    float amax = 0.f;
#pragma unroll
    for (int i = 0; i < 16; i++) {
        f[i] = s4[tid + i * 512];
        amax = fmaxf(amax, fmaxf(fmaxf(fabsf(f[i].x), fabsf(f[i].y)),
                                 fmaxf(fabsf(f[i].z), fabsf(f[i].w))));
    }
#pragma unroll
    for (int o = 16; o > 0; o >>= 1) amax = fmaxf(amax, __shfl_xor_sync(~0u, amax, o));
    if (lane == 0) red[warp] = amax;
    __syncthreads();
    if (tid == 0) {
        float m = red[0];
        for (int w = 1; w < 16; w++) m = fmaxf(m, red[w]);
        red[0] = fmaxf(m, 1e-12f) / 448.0f;
    }
    __syncthreads();
    const float scale = red[0];
    const float inv = 1.0f / scale;

    uint2* dq = reinterpret_cast<uint2*>(g_Vq + base);
#pragma unroll
    for (int i = 0; i < 16; i++) {
        uint2 pk;
        pk.x = quant2h(f[i].x * inv, f[i].y * inv);
        pk.y = quant2h(f[i].z * inv, f[i].w * inv);
        dq[tid + i * 512] = pk;
    }
    if (tid == 0) g_Vs[head * 8 + vb] = scale;
}

// ---------------- attention (Q rotate+quant fused into prologue) -----------
// 256 threads (8 warps), 32 Q rows/warp -> 256 Q rows/CTA, grid 8x16 = 128
// CTAs (single wave). KV tiles of 128, double-buffered, 4x32-col chunks.
// Q/K fp8 rows: 128B data @ 144B stride. V fp16 rows: 256B data @ 272B stride.
#define SQ_   0                           // 256 * 144 = 36864
#define SK0_  36864                       // 128 * 144 = 18432
#define SK1_  55296
#define SV0_  73728                       // 128 * 272 = 34816
#define SV1_  108544
#define SMA_  143424                      // + 64B for reduce scratch
#define SRED_ 143360

__global__ __launch_bounds__(256, 1) void attn_kernel(const float* __restrict__ qg,
                                                      const float* __restrict__ R,
                                                      float* __restrict__ out) {
    extern __shared__ char smc[];
    const uint32_t sb = (uint32_t)__cvta_generic_to_shared(smc);
    const int qb = blockIdx.x, head = blockIdx.y;
    const int kvh = head >> 1;
    const int tid = threadIdx.x, lane = tid & 31, warp = tid >> 5;
    float* red = reinterpret_cast<float*>(smc + SRED_);

    const uint8_t* Kg = g_Kq8 + (long)kvh * SEQ * DIM;
    const __half*  Vg = g_Vq  + (long)kvh * SEQ * DIM;

    // ---- prologue 1: issue K/V tile 0 cp.asyncs ----
#pragma unroll
    for (int i = 0; i < 4; i++) {
        int idx = tid + i * 256;                // 1024 chunks
        int row = idx >> 3, seg = idx & 7;
        cp16(sb + SK0_ + row * 144 + seg * 16, Kg + row * DIM + seg * 16);
    }
#pragma unroll
    for (int i = 0; i < 8; i++) {
        int idx = tid + i * 256;                // 2048 chunks
        int row = idx >> 4, seg = idx & 15;
        cp16(sb + SV0_ + row * 272 + seg * 16, Vg + row * DIM + seg * 8);
    }
    cp_commit();

    // ---- prologue 2: Q rotate + quantize into smem (one pass, reg-held) ----
    // warp w owns rows w*32..w*32+31; warps 0-3 = scale half 0, 4-7 = half 1.
    float qscale;
    {
        const float4* s4 = reinterpret_cast<const float4*>(
            qg + (long)(head * SEQ + qb * 256) * DIM);
        float sg[4];
#pragma unroll
        for (int r = 0; r < 4; r++)
            sg[r] = (R[(4 * lane + r) * DIM] > 0.f) ? 1.f : -1.f;
        const float c = 0.08838834764831843f;   // 1/sqrt(128)

        float w0[32], w1[32], w2[32], w3[32];
        float amax = 0.f;
#pragma unroll
        for (int i = 0; i < 32; i++) {
            const int row = warp * 32 + i;
            float4 f = s4[row * 32 + lane];
            float v0 = f.x * sg[0], v1 = f.y * sg[1], v2 = f.z * sg[2], v3 = f.w * sg[3];
            fwht4(v0, v1, v2, v3, lane);
            w0[i] = v0; w1[i] = v1; w2[i] = v2; w3[i] = v3;
            amax = fmaxf(amax, fmaxf(fmaxf(fabsf(v0), fabsf(v1)), fmaxf(fabsf(v2), fabsf(v3))));
        }
#pragma unroll
        for (int o = 16; o > 0; o >>= 1) amax = fmaxf(amax, __shfl_xor_sync(~0u, amax, o));
        if (lane == 0) red[warp] = amax;
        __syncthreads();
        {
            const int h0 = (warp >> 2) * 4;
            float m = fmaxf(fmaxf(red[h0], red[h0 + 1]), fmaxf(red[h0 + 2], red[h0 + 3]));
            qscale = fmaxf(m * c, 1e-12f) / 448.0f;
        }
        const float inv = 1.0f / qscale;

#pragma unroll
        for (int i = 0; i < 32; i++) {
            const int row = warp * 32 + i;
            uint32_t lo = quant2e((w0[i] * c) * inv, (w1[i] * c) * inv);
            uint32_t hi = quant2e((w2[i] * c) * inv, (w3[i] * c) * inv);
            *reinterpret_cast<uint32_t*>(smc + SQ_ + row * 144 + lane * 4) = lo | (hi << 16);
        }
    }

    cp_wait<0>();
    __syncthreads();

    float oacc[2][16][4];
#pragma unroll
    for (int mf = 0; mf < 2; mf++)
#pragma unroll
        for (int n = 0; n < 16; n++)
#pragma unroll
            for (int c = 0; c < 4; c++) oacc[mf][n][c] = 0.f;
    float denom[4] = {0.f, 0.f, 0.f, 0.f};

    const float RS_LOG2E = 0.08838834764831843f * 1.4426950408889634f;

    // hoisted per-thread addresses
    const uint32_t qbase = sb + SQ_ + (uint32_t)(warp * 32 + (lane & 15)) * 144 +
                           (uint32_t)((lane >> 4) * 16);
    const uint32_t kR = (uint32_t)(((lane & 7) + ((lane >> 4) << 3)) * 144 +
                                   ((lane >> 3) & 1) * 16);
    const uint32_t vR = (uint32_t)(((lane & 7) + (((lane >> 3) & 1) << 3)) * 272 +
                                   ((lane >> 4) * 16));

    for (int t = 0; t < 16; t++) {
        const int p = t & 1;
        const uint32_t kb   = sb + SK0_ + p * 18432;
        const uint32_t vbuf = sb + SV0_ + p * 34816;

        // ---- issue async loads for tile t+1 into the other buffer ----
        if (t < 15) {
            const uint32_t kb2 = sb + SK0_ + (1 - p) * 18432;
            const uint32_t vb2 = sb + SV0_ + (1 - p) * 34816;
            const uint8_t* Kt = Kg + (long)(t + 1) * 128 * DIM;
            const __half*  Vt = Vg + (long)(t + 1) * 128 * DIM;
#pragma unroll
            for (int i = 0; i < 4; i++) {
                int idx = tid + i * 256;
                int row = idx >> 3, seg = idx & 7;
                cp16(kb2 + row * 144 + seg * 16, Kt + row * DIM + seg * 16);
            }
#pragma unroll
            for (int i = 0; i < 8; i++) {
                int idx = tid + i * 256;
                int row = idx >> 4, seg = idx & 15;
                cp16(vb2 + row * 272 + seg * 16, Vt + row * DIM + seg * 8);
            }
            cp_commit();
        }

        const float m  = qscale * g_Ks[kvh * 8 + (t >> 1)] * RS_LOG2E;
        const float sv = g_Vs[kvh * 8 + (t >> 1)];

        // ---- process tile as four 32-kv-col chunks ----
#pragma unroll
        for (int ch = 0; ch < 4; ch++) {
            // S chunk: 32 Q rows x 32 KV cols (fp8, exact)
            float sacc[2][4][4];
#pragma unroll
            for (int mf = 0; mf < 2; mf++)
#pragma unroll
                for (int j = 0; j < 4; j++)
#pragma unroll
                    for (int c = 0; c < 4; c++) sacc[mf][j][c] = 0.f;

#pragma unroll
            for (int kk = 0; kk < 4; kk++) {
                uint32_t q0[4], q1[4];
                ldm4(q0, qbase + kk * 32);              // mf0 rows
                ldm4(q1, qbase + 16 * 144 + kk * 32);   // mf1 rows
#pragma unroll
                for (int jp = 0; jp < 2; jp++) {
                    uint32_t b[4];
                    ldm4(b, kb + kR + (ch * 32 + jp * 16) * 144 + kk * 32);
                    mma16832q(sacc[0][2 * jp],     q0, b[0], b[1]);
                    mma16832q(sacc[0][2 * jp + 1], q0, b[2], b[3]);
                    mma16832q(sacc[1][2 * jp],     q1, b[0], b[1]);
                    mma16832q(sacc[1][2 * jp + 1], q1, b[2], b[3]);
                }
            }

            // softmax (no-max; constant -6 shift cancels), fold V scale
            uint32_t pf[2][4][2];
#pragma unroll
            for (int mf = 0; mf < 2; mf++) {
#pragma unroll
                for (int j = 0; j < 4; j++) {
                    float e0 = fast_ex2(fmaf(sacc[mf][j][0], m, -6.f));
                    float e1 = fast_ex2(fmaf(sacc[mf][j][1], m, -6.f));
                    float e2 = fast_ex2(fmaf(sacc[mf][j][2], m, -6.f));
                    float e3 = fast_ex2(fmaf(sacc[mf][j][3], m, -6.f));
                    denom[2 * mf]     += e0 + e1;
                    denom[2 * mf + 1] += e2 + e3;
                    __half2 h01 = __floats2half2_rn(e0 * sv, e1 * sv);
                    __half2 h23 = __floats2half2_rn(e2 * sv, e3 * sv);
                    pf[mf][j][0] = *reinterpret_cast<uint32_t*>(&h01);
                    pf[mf][j][1] = *reinterpret_cast<uint32_t*>(&h23);
                }
            }

            // O += P . Vraw (fp16): k = 32 (2 k16 steps)
#pragma unroll
            for (int kk = 0; kk < 2; kk++) {
                uint32_t a0[4] = {pf[0][2 * kk][0], pf[0][2 * kk][1],
                                  pf[0][2 * kk + 1][0], pf[0][2 * kk + 1][1]};
                uint32_t a1[4] = {pf[1][2 * kk][0], pf[1][2 * kk][1],
                                  pf[1][2 * kk + 1][0], pf[1][2 * kk + 1][1]};
#pragma unroll
                for (int dp = 0; dp < 8; dp++) {
                    uint32_t b[4];
                    ldm4t(b, vbuf + vR + (ch * 32 + kk * 16) * 272 + dp * 32);
                    mma16816(oacc[0][2 * dp],     a0, b[0], b[1]);
                    mma16816(oacc[0][2 * dp + 1], a0, b[2], b[3]);
                    mma16816(oacc[1][2 * dp],     a1, b[0], b[1]);
                    mma16816(oacc[1][2 * dp + 1], a1, b[2], b[3]);
                }
            }
        }

        if (t < 15) {
            cp_wait<0>();
            __syncthreads();
        }
    }

    // ---- epilogue ----
#pragma unroll
    for (int d = 0; d < 4; d++) {
        denom[d] += __shfl_xor_sync(~0u, denom[d], 1);
        denom[d] += __shfl_xor_sync(~0u, denom[d], 2);
        denom[d] = 1.0f / denom[d];
    }

    float* ob = out + (long)head * SEQ * DIM;
#pragma unroll
    for (int mf = 0; mf < 2; mf++) {
        const int row0 = qb * 256 + warp * 32 + mf * 16 + (lane >> 2);
        const float inv0 = denom[2 * mf], inv1 = denom[2 * mf + 1];
#pragma unroll
        for (int dt = 0; dt < 16; dt++) {
            int col = dt * 8 + (lane & 3) * 2;
            ob[(long)row0 * DIM + col]           = oacc[mf][dt][0] * inv0;
            ob[(long)row0 * DIM + col + 1]       = oacc[mf][dt][1] * inv0;
            ob[(long)(row0 + 8) * DIM + col]     = oacc[mf][dt][2] * inv1;
            ob[(long)(row0 + 8) * DIM + col + 1] = oacc[mf][dt][3] * inv1;
        }
    }
}

// ---------------- host ----------------
extern "C" void kernel_launch(void* const* d_in, const int* in_sizes, int n_in,
                              void* d_out, int out_size) {
    (void)in_sizes; (void)n_in; (void)out_size;
    const float* q = (const float*)d_in[0];
    const float* k = (const float*)d_in[1];
    const float* v = (const float*)d_in[2];
    const float* R = (const float*)d_in[3];
    float* out = (float*)d_out;

    cudaFuncSetAttribute((const void*)attn_kernel,
                         cudaFuncAttributeMaxDynamicSharedMemorySize, SMA_);

    quant_kv<<<128, 512>>>(k, v, R);
    attn_kernel<<<dim3(8, HQ), 256, SMA_>>>(q, R, out);
}